// round 8
// baseline (speedup 1.0000x reference)
#include <cuda_runtime.h>
#include <cstdint>

// CostVolume: out[b,d,h,x] = (1/128) * sum_c L[b,c,h,x]*R[b,c,h,x-d], x>=d else 0
// B=8 C=128 H=128 W=240 V=48
// Parity-phased x-pairing (all R pairs aligned); R staged in smem, L streamed
// from global directly into registers (crossbar relief).
#define B_  8
#define C_  128
#define H_  128
#define W_  240
#define V_  48
#define HW_ (H_*W_)

#define CC   16            // channels per chunk
#define NCH  (C_/CC)       // 8 chunks
#define THREADS 128
#define RW   288           // sR row width: 48 zero pad + 240 data

typedef unsigned long long ull;

__device__ __forceinline__ ull pk(float lo, float hi) {
    ull r; asm("mov.b64 %0, {%1, %2};" : "=l"(r) : "f"(lo), "f"(hi)); return r;
}
__device__ __forceinline__ void upk(ull v, float& lo, float& hi) {
    asm("mov.b64 {%0, %1}, %2;" : "=f"(lo), "=f"(hi) : "l"(v));
}
__device__ __forceinline__ void fma2(ull& acc, ull a, ull b) {
    asm("fma.rn.f32x2 %0, %1, %2, %0;" : "+l"(acc) : "l"(a), "l"(b));
}
__device__ __forceinline__ void cpasync16(uint32_t saddr, const void* g) {
    asm volatile("cp.async.cg.shared.global [%0], [%1], 16;" :: "r"(saddr), "l"(g));
}

__global__ void __launch_bounds__(THREADS, 3)
cv_kernel(const float* __restrict__ L, const float* __restrict__ R,
          float* __restrict__ out)
{
    extern __shared__ float smem[];
    float* sR = smem;                 // [2][CC][RW]

    const int tid = threadIdx.x;
    const int h = blockIdx.x;
    const int b = blockIdx.y;

    const int xg = tid & 63;          // 0..63 (60 active)
    const int ig = tid >> 6;          // 0..1
    const int i0 = ig * 24;           // disparity base for this group
    const int xb = xg * 4;
    const bool act = (xg < 60);

    const float* Lbase = L + ((size_t)b * C_ * H_ + h) * W_;
    const float* Rbase = R + ((size_t)b * C_ * H_ + h) * W_;

    // Zero the left pad of sR (x<0 -> 0), both buffers, once.
    for (int idx = tid; idx < 2 * CC * 48; idx += THREADS) {
        int buf = idx / (CC * 48);
        int rem = idx - buf * (CC * 48);
        int r = rem / 48, k = rem - r * 48;
        sR[buf * (CC * RW) + r * RW + k] = 0.0f;
    }

    // accE[j]: d = i0+2j, x pairs (xb,xb+1),(xb+2,xb+3)
    // accO[j]: d = i0+2j+1, x pairs (xb+1,xb+2),(xb+3,xb+4)
    ull accE[12][2], accO[12][2];
    #pragma unroll
    for (int j = 0; j < 12; j++) {
        accE[j][0] = 0ull; accE[j][1] = 0ull;
        accO[j][0] = 0ull; accO[j][1] = 0ull;
    }

    auto issue_load = [&](int ch, int buf) {
        const int c0 = ch * CC;
        #pragma unroll
        for (int q = 0; q < 8; q++) {            // 960 float4 ops / 128 thr
            int f = tid + q * THREADS;
            if (f < 960) {                        // R tile (offset 48)
                int r = f / 60, col = (f - r * 60) * 4;
                uint32_t d = (uint32_t)__cvta_generic_to_shared(
                    &sR[buf * (CC * RW) + r * RW + 48 + col]);
                cpasync16(d, Rbase + (size_t)(c0 + r) * HW_ + col);
            }
        }
        asm volatile("cp.async.commit_group;");
    };

    issue_load(0, 0);

    #pragma unroll 1
    for (int ch = 0; ch < NCH; ch++) {
        const int buf = ch & 1;
        if (ch + 1 < NCH) {
            issue_load(ch + 1, (ch + 1) & 1);
            asm volatile("cp.async.wait_group 1;");
        } else {
            asm volatile("cp.async.wait_group 0;");
        }
        __syncthreads();

        if (act) {
            const float* bR = &sR[buf * (CC * RW)];
            const float* lp = Lbase + (size_t)ch * CC * HW_ + xb;
            const int ab = xb - i0 + 24;   // window base in padded sR row
            #pragma unroll
            for (int cc = 0; cc < CC; cc++) {
                // L from global (read-only cache); independent across cc ->
                // ptxas batches these ahead (MLP) to cover latency.
                float4 Lq = __ldg((const float4*)(lp + (size_t)cc * HW_));
                float  Ls = (xg < 59) ? __ldg(lp + (size_t)cc * HW_ + 4) : 0.0f;
                ull Le0 = pk(Lq.x, Lq.y);           // aligned: elided
                ull Le1 = pk(Lq.z, Lq.w);
                ull Lo0 = pk(Lq.y, Lq.z);           // 2 MOVs
                ull Lo1 = pk(Lq.w, Ls);             // 2 MOVs

                // P[i] = (R[xb-i0-24+2i], R[xb-i0-24+2i+1]) — aligned pairs
                ull P[14];
                {
                    float2 v1 = *(const float2*)(bR + cc * RW + ab + 2);
                    P[1] = pk(v1.x, v1.y);
                    #pragma unroll
                    for (int m = 0; m < 6; m++) {
                        float4 qv = *(const float4*)(bR + cc * RW + ab + 4 + 4 * m);
                        P[2*m+2] = pk(qv.x, qv.y);
                        P[2*m+3] = pk(qv.z, qv.w);
                    }
                }

                #pragma unroll
                for (int j = 0; j < 12; j++) {
                    fma2(accE[j][0], Le0, P[12 - j]);
                    fma2(accO[j][0], Lo0, P[12 - j]);
                    fma2(accE[j][1], Le1, P[13 - j]);
                    fma2(accO[j][1], Lo1, P[13 - j]);
                }
            }
        }
        __syncthreads();
    }

    const float s = 1.0f / 128.0f;
    if (act) {
        #pragma unroll
        for (int j = 0; j < 12; j++) {
            const int de = i0 + 2 * j;
            float a0, a1, a2, a3;
            upk(accE[j][0], a0, a1);
            upk(accE[j][1], a2, a3);
            float4 o;
            o.x = a0 * s; o.y = a1 * s; o.z = a2 * s; o.w = a3 * s;
            *(float4*)(out + (((size_t)b * V_ + de) * H_ + h) * W_ + xb) = o;

            float b0, b1, b2, b3;
            upk(accO[j][0], b0, b1);
            upk(accO[j][1], b2, b3);
            float* oo = out + (((size_t)b * V_ + de + 1) * H_ + h) * W_ + xb;
            oo[1] = b0 * s;
            oo[2] = b1 * s;
            oo[3] = b2 * s;
            if (xg < 59) oo[4] = b3 * s;     // x=xb+4; skip x=240 (lane 59)
        }
    } else if (xg == 60) {
        // out[x=0, odd d] never produced by the odd pipeline; it's 0 (x<d).
        #pragma unroll
        for (int j = 0; j < 12; j++) {
            const int d = i0 + 2 * j + 1;
            out[(((size_t)b * V_ + d) * H_ + h) * W_] = 0.0f;
        }
    }
}

extern "C" void kernel_launch(void* const* d_in, const int* in_sizes, int n_in,
                              void* d_out, int out_size)
{
    const float* L = (const float*)d_in[0];
    const float* R = (const float*)d_in[1];
    float* out = (float*)d_out;

    const int smem_bytes = 2 * CC * RW * (int)sizeof(float);   // 36864
    cudaFuncSetAttribute(cv_kernel, cudaFuncAttributeMaxDynamicSharedMemorySize,
                         smem_bytes);
    cv_kernel<<<dim3(H_, B_), THREADS, smem_bytes>>>(L, R, out);
}